// round 16
// baseline (speedup 1.0000x reference)
#include <cuda_runtime.h>
#include <cuda_fp16.h>
#include <stdint.h>
#include <math.h>

#define T_DIM   4096
#define B_DIM   8
#define M_TOK   32768
#define CHAN    8192
#define BH_DIM  128

// ---------------------------------------------------------------------------
// Device-global scratch
// ---------------------------------------------------------------------------
__device__ __half g_A  [M_TOK * 1024];
__device__ __half g_M  [M_TOK * 4096];
__device__ __half g_W1 [2048 * 1024];                      // permuted (a/gate interleaved)
__device__ __half g_W2 [1024 * 1024];
__device__ __half g_Wf1[4096 * 1024];
__device__ __half g_Wf2[1024 * 4096];
__device__ __half g_Woh[16 * 1024];                        // W_off transposed fp16
__device__ __half g_glu[M_TOK * 1024];
__device__ float g_y   [M_TOK * 1024];
__device__ float g_alpha[T_DIM * BH_DIM];
__device__ float g_part[8 * CHAN];

__device__ __forceinline__ float sigmoidf_(float v) { return 1.f / (1.f + __expf(-v)); }

__device__ __forceinline__ uint32_t smem_addr_of(const void* p) {
    uint32_t a;
    asm("{ .reg .u64 t; cvta.to.shared.u64 t, %1; cvt.u32.u64 %0, t; }" : "=r"(a) : "l"(p));
    return a;
}
__device__ __forceinline__ void ldsm4(uint32_t* r, uint32_t addr) {
    asm volatile("ldmatrix.sync.aligned.m8n8.x4.shared.b16 {%0,%1,%2,%3}, [%4];"
                 : "=r"(r[0]), "=r"(r[1]), "=r"(r[2]), "=r"(r[3]) : "r"(addr));
}
__device__ __forceinline__ void mma16816h(float* d, const uint32_t* a, const uint32_t* b) {
    asm volatile("mma.sync.aligned.m16n8k16.row.col.f32.f16.f16.f32 "
                 "{%0,%1,%2,%3}, {%4,%5,%6,%7}, {%8,%9}, {%0,%1,%2,%3};"
                 : "+f"(d[0]), "+f"(d[1]), "+f"(d[2]), "+f"(d[3])
                 : "r"(a[0]), "r"(a[1]), "r"(a[2]), "r"(a[3]), "r"(b[0]), "r"(b[1]));
}
__device__ __forceinline__ void cpa16(uint32_t s, const void* g) {
    asm volatile("cp.async.cg.shared.global [%0], [%1], 16;" :: "r"(s), "l"(g));
}
__device__ __forceinline__ void cpa_commit() {
    asm volatile("cp.async.commit_group;" ::: "memory");
}
__device__ __forceinline__ void cpa_wait1() {
    asm volatile("cp.async.wait_group 1;" ::: "memory");
}

// ---------------------------------------------------------------------------
// fp16 GEMM on mma.sync: C = A_fp16 @ B_fp16^T, fp32 accumulate.
// CTA 128x128, 8 warps (64x32 warp tile), BK=64 (128B rows, XOR-8 swizzle),
// 3-stage cp.async ring -> 96KB smem -> 2 CTAs/SM. K compile-time.
// EPI: 1 = +bias, swish -> fp16 ; 2 = +bias + residual -> fp32 ;
//      3 = GLU (paired cols a/gate) +bias -> fp16 glu [M, N/2]
// ---------------------------------------------------------------------------
#define TILE_B  16384
#define STAGE_B 32768
#define GEMM_SMEM (3 * STAGE_B)

template<int EPI, int K>
__global__ __launch_bounds__(256, 2) void gemm_mma(
    const __half* __restrict__ A, const __half* __restrict__ B,
    const float* __restrict__ bias, const float* __restrict__ res,
    float* __restrict__ C, __half* __restrict__ Ch,
    int M, int N)
{
    extern __shared__ __align__(1024) char smem[];
    const uint32_t sb = smem_addr_of(smem);
    const int tid = threadIdx.x, wid = tid >> 5, lane = tid & 31;
    const int wm = wid & 1, wn = wid >> 1;
    const int m0 = blockIdx.y << 7, n0 = blockIdx.x << 7;

    const __half* gA = A + (size_t)m0 * K;
    const __half* gB = B + (size_t)n0 * K;

    const int ldr = tid >> 3;
    const int ldc = tid & 7;
    const uint32_t dst = (uint32_t)ldr * 128 + (((uint32_t)ldc ^ (ldr & 7)) << 4);

    auto load_stage = [&](uint32_t sbase, int chunk) {
        const int k0 = chunk << 6;
        const __half* a = gA + (size_t)ldr * K + k0 + (ldc << 3);
        const __half* b = gB + (size_t)ldr * K + k0 + (ldc << 3);
        #pragma unroll
        for (int i = 0; i < 4; i++) {
            cpa16(sbase + dst + i * (32 * 128), a + (size_t)(i * 32) * K);
            cpa16(sbase + TILE_B + dst + i * (32 * 128), b + (size_t)(i * 32) * K);
        }
    };

    float acc[4][4][4];
    #pragma unroll
    for (int a = 0; a < 4; a++)
        #pragma unroll
        for (int b = 0; b < 4; b++)
            #pragma unroll
            for (int k = 0; k < 4; k++) acc[a][b][k] = 0.f;

    constexpr int NC = K >> 6;
    uint32_t st0 = sb, st1 = sb + STAGE_B, st2 = sb + 2 * STAGE_B;
    load_stage(st0, 0); cpa_commit();
    load_stage(st1, 1); cpa_commit();

    const int ar = (wm << 6) + (lane & 15);
    const uint32_t aRow = (uint32_t)ar * 128;
    const int axor = ar & 7;
    const int ahalf = lane >> 4;
    const int br = (wn << 5) + ((lane & 7) | ((lane & 16) >> 1));
    const uint32_t bRow = (uint32_t)br * 128;
    const int bxor = br & 7;
    const int bhalf = (lane >> 3) & 1;

    #pragma unroll 1
    for (int c = 0; c < NC; c++) {
        cpa_wait1();
        __syncthreads();
        if (c + 2 < NC) load_stage(st2, c + 2);
        cpa_commit();

        const uint32_t aH = st0 + aRow;
        const uint32_t bH = st0 + TILE_B + bRow;

        #pragma unroll
        for (int kk = 0; kk < 4; kk++) {
            const uint32_t acol = (uint32_t)((((kk << 1) + ahalf) ^ axor)) << 4;
            const uint32_t bcol = (uint32_t)((((kk << 1) + bhalf) ^ bxor)) << 4;
            uint32_t bh[2][4];
            ldsm4(bh[0], bH + bcol);
            ldsm4(bh[1], bH + (16 * 128) + bcol);
            #pragma unroll
            for (int fm = 0; fm < 4; fm++) {
                uint32_t a_f[4];
                ldsm4(a_f, aH + fm * (16 * 128) + acol);
                #pragma unroll
                for (int fn = 0; fn < 4; fn++)
                    mma16816h(acc[fm][fn], a_f, &bh[fn >> 1][(fn & 1) << 1]);
            }
        }
        const uint32_t t = st0; st0 = st1; st1 = st2; st2 = t;
    }

    // ---- epilogue ----
    const int mB = m0 + (wm << 6) + (lane >> 2);
    const int nB = n0 + (wn << 5) + ((lane & 3) << 1);
    #pragma unroll
    for (int fm = 0; fm < 4; fm++) {
        const int r0 = mB + (fm << 4);
        #pragma unroll
        for (int fn = 0; fn < 4; fn++) {
            const int cc = nB + (fn << 3);
            if (EPI == 3) {
                const int j = cc >> 1;
                const float ba = __ldg(bias + j);
                const float bg = __ldg(bias + 1024 + j);
                const float a0 = acc[fm][fn][0] + ba, gg0 = acc[fm][fn][1] + bg;
                const float a1 = acc[fm][fn][2] + ba, gg1 = acc[fm][fn][3] + bg;
                Ch[(size_t)r0 * (N >> 1) + j]       = __float2half_rn(a0 * sigmoidf_(gg0));
                Ch[(size_t)(r0 + 8) * (N >> 1) + j] = __float2half_rn(a1 * sigmoidf_(gg1));
            } else {
                const float2 bv = __ldg((const float2*)(bias + cc));
                float v0 = acc[fm][fn][0] + bv.x;
                float v1 = acc[fm][fn][1] + bv.y;
                float v2 = acc[fm][fn][2] + bv.x;
                float v3 = acc[fm][fn][3] + bv.y;
                const size_t o0 = (size_t)r0 * N + cc;
                const size_t o1 = (size_t)(r0 + 8) * N + cc;
                if (EPI == 1) {
                    v0 = v0 * sigmoidf_(v0); v1 = v1 * sigmoidf_(v1);
                    v2 = v2 * sigmoidf_(v2); v3 = v3 * sigmoidf_(v3);
                    __half2 p;
                    p.x = __float2half_rn(v0); p.y = __float2half_rn(v1);
                    *(__half2*)(Ch + o0) = p;
                    p.x = __float2half_rn(v2); p.y = __float2half_rn(v3);
                    *(__half2*)(Ch + o1) = p;
                } else {
                    const float2 ra = __ldg((const float2*)(res + o0));
                    const float2 rb = __ldg((const float2*)(res + o1));
                    v0 += ra.x; v1 += ra.y; v2 += rb.x; v3 += rb.y;
                    float2 q;
                    q.x = v0; q.y = v1; *(float2*)(C + o0) = q;
                    q.x = v2; q.y = v3; *(float2*)(C + o1) = q;
                }
            }
        }
    }
}

// ---------------------------------------------------------------------------
// Merged weight convert + transpose for all 4 weights + W_off (one launch).
// Blocks [0,2048) W1 perm, [2048,3072) W2, [3072,7168) Wf1, [7168,11264) Wf2,
// block 11264: W_off -> fp16 transposed [16][1024].
// ---------------------------------------------------------------------------
__global__ __launch_bounds__(256) void wconv_all(
    const float* __restrict__ W1, const float* __restrict__ W2,
    const float* __restrict__ Wf1, const float* __restrict__ Wf2,
    const float* __restrict__ Woff,
    __half* __restrict__ W1p, __half* __restrict__ W2p,
    __half* __restrict__ Wf1p, __half* __restrict__ Wf2p,
    __half* __restrict__ Woh)
{
    __shared__ float tile[32][33];
    const int bid = blockIdx.x;
    const int tx = threadIdx.x, ty = threadIdx.y;

    if (bid == 11264) {
        const int tid = ty * 32 + tx;
        for (int i = tid; i < 16384; i += 256) {
            const int n = i & 15, k = i >> 4;
            Woh[n * 1024 + k] = __float2half_rn(Woff[(size_t)k * 16 + n]);
        }
        return;
    }

    const float* W; __half* Wh;
    int K, N, n0, k0;
    bool perm = false;
    if (bid < 2048)       { perm = true; W = W1;  Wh = W1p;  K = 1024; N = 2048;
                            n0 = (bid & 63) << 5;  k0 = (bid >> 6) << 5; }
    else if (bid < 3072)  { const int r = bid - 2048; W = W2;  Wh = W2p;  K = 1024; N = 1024;
                            n0 = (r & 31) << 5;    k0 = (r >> 5) << 5; }
    else if (bid < 7168)  { const int r = bid - 3072; W = Wf1; Wh = Wf1p; K = 1024; N = 4096;
                            n0 = (r & 127) << 5;   k0 = (r >> 7) << 5; }
    else                  { const int r = bid - 7168; W = Wf2; Wh = Wf2p; K = 4096; N = 1024;
                            n0 = (r & 31) << 5;    k0 = (r >> 5) << 5; }

    if (perm) {
        const int orow = n0 + tx;
        const int scol = (orow & 1) ? (1024 + (orow >> 1)) : (orow >> 1);
        for (int i = ty; i < 32; i += 8)
            tile[i][tx] = W[(size_t)(k0 + i) * 2048 + scol];
    } else {
        for (int i = ty; i < 32; i += 8)
            tile[i][tx] = W[(size_t)(k0 + i) * N + n0 + tx];
    }
    __syncthreads();
    for (int i = ty; i < 32; i += 8)
        Wh[(size_t)(n0 + i) * K + k0 + tx] = __float2half_rn(tile[tx][i]);
}

// ---------------------------------------------------------------------------
// LayerNorm -> fp16, warp per row (no block barriers)
// ---------------------------------------------------------------------------
__global__ __launch_bounds__(256) void ln_h_kernel(
    const float* __restrict__ in, __half* __restrict__ oh,
    const float* __restrict__ gw, const float* __restrict__ bw)
{
    const int wid = threadIdx.x >> 5, lane = threadIdx.x & 31;
    const size_t row = (size_t)blockIdx.x * 8 + wid;
    const float4* ip = (const float4*)(in + row * 1024);

    float4 v[8];
    #pragma unroll
    for (int j = 0; j < 8; j++) v[j] = ip[j * 32 + lane];

    float s = 0.f;
    #pragma unroll
    for (int j = 0; j < 8; j++) s += v[j].x + v[j].y + v[j].z + v[j].w;
    #pragma unroll
    for (int o = 16; o > 0; o >>= 1) s += __shfl_xor_sync(0xffffffffu, s, o);
    const float mean = s * (1.f / 1024.f);

    float q = 0.f;
    #pragma unroll
    for (int j = 0; j < 8; j++) {
        const float dx = v[j].x - mean, dy = v[j].y - mean;
        const float dz = v[j].z - mean, dw = v[j].w - mean;
        q += dx * dx + dy * dy + dz * dz + dw * dw;
    }
    #pragma unroll
    for (int o = 16; o > 0; o >>= 1) q += __shfl_xor_sync(0xffffffffu, q, o);
    const float rstd = rsqrtf(q * (1.f / 1024.f) + 1e-5f);

    #pragma unroll
    for (int j = 0; j < 8; j++) {
        const int i4 = j * 32 + lane;
        const float4 g4 = __ldg((const float4*)gw + i4);
        const float4 b4 = __ldg((const float4*)bw + i4);
        const size_t base = row * 1024 + (size_t)i4 * 4;
        __half2 p;
        p.x = __float2half_rn((v[j].x - mean) * rstd * g4.x + b4.x);
        p.y = __float2half_rn((v[j].y - mean) * rstd * g4.y + b4.y);
        *(__half2*)(oh + base) = p;
        p.x = __float2half_rn((v[j].z - mean) * rstd * g4.z + b4.z);
        p.y = __float2half_rn((v[j].w - mean) * rstd * g4.w + b4.w);
        *(__half2*)(oh + base + 2) = p;
    }
}

// ---------------------------------------------------------------------------
// Merged alpha + cumsum_part. Blocks [0,1024): alpha, 4 rows/warp, fp16 W_off
// in smem (32KB). Blocks [1024,1280): partial segment sums.
// ---------------------------------------------------------------------------
__global__ __launch_bounds__(256) void alpha_part_kernel(
    const __half* __restrict__ g, const __half* __restrict__ Woh,
    const float* __restrict__ boff, float* __restrict__ alpha,
    float* __restrict__ part)
{
    if (blockIdx.x >= 1024) {
        const int u = (blockIdx.x - 1024) * 256 + threadIdx.x;
        const int c = u & 8191;
        const int s = u >> 13;
        float acc = 0.f;
        for (int t0 = s * 512; t0 < (s + 1) * 512; t0 += 8) {
            float v[8];
            #pragma unroll
            for (int i = 0; i < 8; i++)
                v[i] = __half2float(g[(size_t)(t0 + i) * CHAN + c]);
            #pragma unroll
            for (int i = 0; i < 8; i++) acc += v[i];
        }
        part[s * CHAN + c] = acc;
        return;
    }

    // ---- alpha: warp handles 4 consecutive rows; Ws fp16 [16][1024] ----
    extern __shared__ __half Ws[];
    for (int i = threadIdx.x; i < 2048; i += 256)
        ((uint4*)Ws)[i] = ((const uint4*)Woh)[i];
    __syncthreads();

    const int wid = threadIdx.x >> 5, lane = threadIdx.x & 31;
    const int row0 = blockIdx.x * 32 + wid * 4;

    float acc[4][16];
    #pragma unroll
    for (int r = 0; r < 4; r++)
        #pragma unroll
        for (int n = 0; n < 16; n++) acc[r][n] = 0.f;

    #pragma unroll
    for (int j = 0; j < 8; j++) {
        const int k = (lane << 2) + (j << 7);
        float f[4][4];
        #pragma unroll
        for (int r = 0; r < 4; r++) {
            const __half* gr = g + (size_t)(row0 + r) * 1024 + k;
            const float2 a = __half22float2(*(const __half2*)gr);
            const float2 b = __half22float2(*(const __half2*)(gr + 2));
            f[r][0] = a.x; f[r][1] = a.y; f[r][2] = b.x; f[r][3] = b.y;
        }
        #pragma unroll
        for (int n = 0; n < 16; n++) {
            const __half2 wa = *(const __half2*)(Ws + n * 1024 + k);
            const __half2 wb = *(const __half2*)(Ws + n * 1024 + k + 2);
            const float2 w0 = __half22float2(wa);
            const float2 w1 = __half22float2(wb);
            #pragma unroll
            for (int r = 0; r < 4; r++)
                acc[r][n] += f[r][0] * w0.x + f[r][1] * w0.y + f[r][2] * w1.x + f[r][3] * w1.y;
        }
    }
    #pragma unroll
    for (int o = 16; o > 0; o >>= 1)
        #pragma unroll
        for (int r = 0; r < 4; r++)
            #pragma unroll
            for (int n = 0; n < 16; n++)
                acc[r][n] += __shfl_xor_sync(0xffffffffu, acc[r][n], o);

    if (lane < 16) {
        #pragma unroll
        for (int r = 0; r < 4; r++) {
            const int row = row0 + r;
            const int t = row >> 3, b = row & 7;
            alpha[(size_t)t * BH_DIM + b * 16 + lane] =
                sigmoidf_(acc[r][lane] + __ldg(boff + lane));
        }
    }
}

// ---------------------------------------------------------------------------
// Fused cumsum-scan + TaLK (fp16 in/out), smem ring of S window.
// ---------------------------------------------------------------------------
__global__ __launch_bounds__(256) void scan_talk_kernel(
    const __half* __restrict__ in, const float* __restrict__ part,
    const float* __restrict__ alpha, __half* __restrict__ oh)
{
    extern __shared__ float ring[];   // [64][256]
    const int tidx = threadIdx.x;
    const int c = blockIdx.x * 256 + tidx;
    const int s = blockIdx.y;
    const int bh = c >> 6;
    const float scale = 1.f / 32.f;

    float acc = 0.f;
    for (int p = 0; p < s; p++) acc += part[p * CHAN + c];
    acc *= scale;

    const int tbase = s * 512;
    if (s > 0) {
        float w[34];
        #pragma unroll
        for (int i = 0; i < 34; i++)
            w[i] = __half2float(in[(size_t)(tbase - 34 + i) * CHAN + c]);
        float sub = 0.f;
        #pragma unroll
        for (int i = 0; i < 34; i++) sub += w[i];
        acc = acc - sub * scale;
        #pragma unroll
        for (int i = 0; i < 34; i++) {
            acc = fmaf(w[i], scale, acc);
            ring[((tbase - 34 + i) & 63) * 256 + tidx] = acc;
        }
    }

    for (int t0 = tbase; t0 < tbase + 512; t0 += 8) {
        float v[8];
        #pragma unroll
        for (int i = 0; i < 8; i++)
            v[i] = __half2float(in[(size_t)(t0 + i) * CHAN + c]);
        float sreg[8];
        #pragma unroll
        for (int i = 0; i < 8; i++) {
            acc = fmaf(v[i], scale, acc);
            sreg[i] = acc;
            ring[((t0 + i) & 63) * 256 + tidx] = acc;
        }
        float al[8];
        #pragma unroll
        for (int i = 0; i < 8; i++)
            al[i] = __ldg(alpha + (size_t)(t0 + i) * BH_DIM + bh);
        #pragma unroll
        for (int i = 0; i < 8; i++) {
            const int t = t0 + i;
            const float eff = fminf(31.f, (float)t);
            const float pos = (float)t - 1.f - al[i] * eff;
            const float i0f = floorf(pos);
            const float frac = pos - i0f;
            const int i0 = (int)i0f;
            const int c0 = max(i0, 0);
            const int c1 = i0 + 1;
            const float v0 = (i0 < 0) ? 0.f : ring[(c0 & 63) * 256 + tidx];
            const float v1 = ring[(c1 & 63) * 256 + tidx];
            const float out = sreg[i] - (v0 + frac * (v1 - v0));
            oh[(size_t)t * CHAN + c] = __float2half_rn(out);
        }
    }
}

// ---------------------------------------------------------------------------
// Launch (single stream, no host objects)
// ---------------------------------------------------------------------------
extern "C" void kernel_launch(void* const* d_in, const int* in_sizes, int n_in,
                              void* d_out, int out_size)
{
    const float* x    = (const float*)d_in[0];
    const float* W1   = (const float*)d_in[4];
    const float* b1   = (const float*)d_in[5];
    const float* Woff = (const float*)d_in[6];
    const float* boff = (const float*)d_in[7];
    const float* W2   = (const float*)d_in[8];
    const float* b2   = (const float*)d_in[9];
    const float* Wf1  = (const float*)d_in[10];
    const float* bf1  = (const float*)d_in[11];
    const float* Wf2  = (const float*)d_in[12];
    const float* bf2  = (const float*)d_in[13];
    const float* gcv  = (const float*)d_in[14];
    const float* bcv  = (const float*)d_in[15];
    const float* gfn  = (const float*)d_in[16];
    const float* bfn  = (const float*)d_in[17];

    __half *Ap, *Mp, *W1p, *W2p, *Wf1p, *Wf2p, *Woh, *glu;
    float *y, *alpha, *part;
    cudaGetSymbolAddress((void**)&Ap, g_A);
    cudaGetSymbolAddress((void**)&Mp, g_M);
    cudaGetSymbolAddress((void**)&W1p, g_W1);
    cudaGetSymbolAddress((void**)&W2p, g_W2);
    cudaGetSymbolAddress((void**)&Wf1p, g_Wf1);
    cudaGetSymbolAddress((void**)&Wf2p, g_Wf2);
    cudaGetSymbolAddress((void**)&Woh, g_Woh);
    cudaGetSymbolAddress((void**)&glu, g_glu);
    cudaGetSymbolAddress((void**)&y, g_y);
    cudaGetSymbolAddress((void**)&alpha, g_alpha);
    cudaGetSymbolAddress((void**)&part, g_part);

    cudaFuncSetAttribute((const void*)gemm_mma<1, 1024>, cudaFuncAttributeMaxDynamicSharedMemorySize, GEMM_SMEM);
    cudaFuncSetAttribute((const void*)gemm_mma<2, 1024>, cudaFuncAttributeMaxDynamicSharedMemorySize, GEMM_SMEM);
    cudaFuncSetAttribute((const void*)gemm_mma<3, 1024>, cudaFuncAttributeMaxDynamicSharedMemorySize, GEMM_SMEM);
    cudaFuncSetAttribute((const void*)gemm_mma<2, 4096>, cudaFuncAttributeMaxDynamicSharedMemorySize, GEMM_SMEM);
    cudaFuncSetAttribute(alpha_part_kernel, cudaFuncAttributeMaxDynamicSharedMemorySize, 32768);
    cudaFuncSetAttribute(scan_talk_kernel, cudaFuncAttributeMaxDynamicSharedMemorySize, 65536);

    // one launch: all weight conversions (+ W_off fp16 transpose)
    wconv_all<<<11265, dim3(32, 8)>>>(W1, W2, Wf1, Wf2, Woff,
                                      W1p, W2p, Wf1p, Wf2p, Woh);

    // conv block
    ln_h_kernel<<<M_TOK / 8, 256>>>(x, Ap, gcv, bcv);
    gemm_mma<3, 1024><<<dim3(16, 256), 256, GEMM_SMEM>>>(
        Ap, W1p, b1, nullptr, nullptr, glu, M_TOK, 2048);
    alpha_part_kernel<<<1024 + 256, 256, 32768>>>(glu, Woh, boff, alpha, part);
    scan_talk_kernel<<<dim3(CHAN / 256, 8), 256, 65536>>>(glu, part, alpha, Ap);
    gemm_mma<2, 1024><<<dim3(8, 256), 256, GEMM_SMEM>>>(
        Ap, W2p, b2, x, y, nullptr, M_TOK, 1024);

    // FFN block
    ln_h_kernel<<<M_TOK / 8, 256>>>(y, Ap, gfn, bfn);
    gemm_mma<1, 1024><<<dim3(32, 256), 256, GEMM_SMEM>>>(
        Ap, Wf1p, bf1, nullptr, nullptr, Mp, M_TOK, 4096);
    gemm_mma<2, 4096><<<dim3(8, 256), 256, GEMM_SMEM>>>(
        Mp, Wf2p, bf2, y, (float*)d_out, nullptr, M_TOK, 1024);
}

// round 17
// speedup vs baseline: 1.0202x; 1.0202x over previous
#include <cuda_runtime.h>
#include <cuda_fp16.h>
#include <stdint.h>
#include <math.h>

#define T_DIM   4096
#define B_DIM   8
#define M_TOK   32768
#define CHAN    8192
#define BH_DIM  128

// ---------------------------------------------------------------------------
// Device-global scratch
// ---------------------------------------------------------------------------
__device__ __half g_A  [M_TOK * 1024];
__device__ __half g_M  [M_TOK * 4096];
__device__ __half g_W1 [2048 * 1024];                      // permuted (a/gate interleaved)
__device__ __half g_W2 [1024 * 1024];
__device__ __half g_Wf1[4096 * 1024];
__device__ __half g_Wf2[1024 * 4096];
__device__ __half g_Woh[16 * 1024];                        // W_off transposed fp16
__device__ __half g_glu[M_TOK * 1024];
__device__ float g_y   [M_TOK * 1024];
__device__ float g_alpha[T_DIM * BH_DIM];
__device__ float g_part[8 * CHAN];

__device__ __forceinline__ float sigmoidf_(float v) { return 1.f / (1.f + __expf(-v)); }

__device__ __forceinline__ uint32_t smem_addr_of(const void* p) {
    uint32_t a;
    asm("{ .reg .u64 t; cvta.to.shared.u64 t, %1; cvt.u32.u64 %0, t; }" : "=r"(a) : "l"(p));
    return a;
}
__device__ __forceinline__ void ldsm4(uint32_t* r, uint32_t addr) {
    asm volatile("ldmatrix.sync.aligned.m8n8.x4.shared.b16 {%0,%1,%2,%3}, [%4];"
                 : "=r"(r[0]), "=r"(r[1]), "=r"(r[2]), "=r"(r[3]) : "r"(addr));
}
__device__ __forceinline__ void mma16816h(float* d, const uint32_t* a, const uint32_t* b) {
    asm volatile("mma.sync.aligned.m16n8k16.row.col.f32.f16.f16.f32 "
                 "{%0,%1,%2,%3}, {%4,%5,%6,%7}, {%8,%9}, {%0,%1,%2,%3};"
                 : "+f"(d[0]), "+f"(d[1]), "+f"(d[2]), "+f"(d[3])
                 : "r"(a[0]), "r"(a[1]), "r"(a[2]), "r"(a[3]), "r"(b[0]), "r"(b[1]));
}
__device__ __forceinline__ void cpa16(uint32_t s, const void* g) {
    asm volatile("cp.async.cg.shared.global [%0], [%1], 16;" :: "r"(s), "l"(g));
}
__device__ __forceinline__ void cpa_commit() {
    asm volatile("cp.async.commit_group;" ::: "memory");
}
__device__ __forceinline__ void cpa_wait1() {
    asm volatile("cp.async.wait_group 1;" ::: "memory");
}

// ---------------------------------------------------------------------------
// fp16 GEMM on mma.sync: C = A_fp16 @ B_fp16^T, fp32 accumulate.
// CTA 128x128, 8 warps (64x32 warp tile), BK=64 (128B rows, XOR-8 swizzle),
// 3-stage cp.async ring -> 96KB smem -> 2 CTAs/SM. K compile-time.
// EPI: 1 = +bias, swish -> fp16 ; 2 = +bias + residual -> fp32 ;
//      3 = GLU (paired cols a/gate) +bias -> fp16 glu [M, N/2]
// ---------------------------------------------------------------------------
#define TILE_B  16384
#define STAGE_B 32768
#define GEMM_SMEM (3 * STAGE_B)

template<int EPI, int K>
__global__ __launch_bounds__(256, 2) void gemm_mma(
    const __half* __restrict__ A, const __half* __restrict__ B,
    const float* __restrict__ bias, const float* __restrict__ res,
    float* __restrict__ C, __half* __restrict__ Ch,
    int M, int N)
{
    extern __shared__ __align__(1024) char smem[];
    const uint32_t sb = smem_addr_of(smem);
    const int tid = threadIdx.x, wid = tid >> 5, lane = tid & 31;
    const int wm = wid & 1, wn = wid >> 1;
    const int m0 = blockIdx.y << 7, n0 = blockIdx.x << 7;

    const __half* gA = A + (size_t)m0 * K;
    const __half* gB = B + (size_t)n0 * K;

    const int ldr = tid >> 3;
    const int ldc = tid & 7;
    const uint32_t dst = (uint32_t)ldr * 128 + (((uint32_t)ldc ^ (ldr & 7)) << 4);

    auto load_stage = [&](uint32_t sbase, int chunk) {
        const int k0 = chunk << 6;
        const __half* a = gA + (size_t)ldr * K + k0 + (ldc << 3);
        const __half* b = gB + (size_t)ldr * K + k0 + (ldc << 3);
        #pragma unroll
        for (int i = 0; i < 4; i++) {
            cpa16(sbase + dst + i * (32 * 128), a + (size_t)(i * 32) * K);
            cpa16(sbase + TILE_B + dst + i * (32 * 128), b + (size_t)(i * 32) * K);
        }
    };

    float acc[4][4][4];
    #pragma unroll
    for (int a = 0; a < 4; a++)
        #pragma unroll
        for (int b = 0; b < 4; b++)
            #pragma unroll
            for (int k = 0; k < 4; k++) acc[a][b][k] = 0.f;

    constexpr int NC = K >> 6;
    uint32_t st0 = sb, st1 = sb + STAGE_B, st2 = sb + 2 * STAGE_B;
    load_stage(st0, 0); cpa_commit();
    load_stage(st1, 1); cpa_commit();

    const int ar = (wm << 6) + (lane & 15);
    const uint32_t aRow = (uint32_t)ar * 128;
    const int axor = ar & 7;
    const int ahalf = lane >> 4;
    const int br = (wn << 5) + ((lane & 7) | ((lane & 16) >> 1));
    const uint32_t bRow = (uint32_t)br * 128;
    const int bxor = br & 7;
    const int bhalf = (lane >> 3) & 1;

    #pragma unroll 1
    for (int c = 0; c < NC; c++) {
        cpa_wait1();
        __syncthreads();
        if (c + 2 < NC) load_stage(st2, c + 2);
        cpa_commit();

        const uint32_t aH = st0 + aRow;
        const uint32_t bH = st0 + TILE_B + bRow;

        #pragma unroll
        for (int kk = 0; kk < 4; kk++) {
            const uint32_t acol = (uint32_t)((((kk << 1) + ahalf) ^ axor)) << 4;
            const uint32_t bcol = (uint32_t)((((kk << 1) + bhalf) ^ bxor)) << 4;
            uint32_t bh[2][4];
            ldsm4(bh[0], bH + bcol);
            ldsm4(bh[1], bH + (16 * 128) + bcol);
            #pragma unroll
            for (int fm = 0; fm < 4; fm++) {
                uint32_t a_f[4];
                ldsm4(a_f, aH + fm * (16 * 128) + acol);
                #pragma unroll
                for (int fn = 0; fn < 4; fn++)
                    mma16816h(acc[fm][fn], a_f, &bh[fn >> 1][(fn & 1) << 1]);
            }
        }
        const uint32_t t = st0; st0 = st1; st1 = st2; st2 = t;
    }

    // ---- epilogue ----
    const int mB = m0 + (wm << 6) + (lane >> 2);
    const int nB = n0 + (wn << 5) + ((lane & 3) << 1);
    #pragma unroll
    for (int fm = 0; fm < 4; fm++) {
        const int r0 = mB + (fm << 4);
        #pragma unroll
        for (int fn = 0; fn < 4; fn++) {
            const int cc = nB + (fn << 3);
            if (EPI == 3) {
                const int j = cc >> 1;
                const float ba = __ldg(bias + j);
                const float bg = __ldg(bias + 1024 + j);
                const float a0 = acc[fm][fn][0] + ba, gg0 = acc[fm][fn][1] + bg;
                const float a1 = acc[fm][fn][2] + ba, gg1 = acc[fm][fn][3] + bg;
                Ch[(size_t)r0 * (N >> 1) + j]       = __float2half_rn(a0 * sigmoidf_(gg0));
                Ch[(size_t)(r0 + 8) * (N >> 1) + j] = __float2half_rn(a1 * sigmoidf_(gg1));
            } else {
                const float2 bv = __ldg((const float2*)(bias + cc));
                float v0 = acc[fm][fn][0] + bv.x;
                float v1 = acc[fm][fn][1] + bv.y;
                float v2 = acc[fm][fn][2] + bv.x;
                float v3 = acc[fm][fn][3] + bv.y;
                const size_t o0 = (size_t)r0 * N + cc;
                const size_t o1 = (size_t)(r0 + 8) * N + cc;
                if (EPI == 1) {
                    v0 = v0 * sigmoidf_(v0); v1 = v1 * sigmoidf_(v1);
                    v2 = v2 * sigmoidf_(v2); v3 = v3 * sigmoidf_(v3);
                    __half2 p;
                    p.x = __float2half_rn(v0); p.y = __float2half_rn(v1);
                    *(__half2*)(Ch + o0) = p;
                    p.x = __float2half_rn(v2); p.y = __float2half_rn(v3);
                    *(__half2*)(Ch + o1) = p;
                } else {
                    const float2 ra = __ldg((const float2*)(res + o0));
                    const float2 rb = __ldg((const float2*)(res + o1));
                    v0 += ra.x; v1 += ra.y; v2 += rb.x; v3 += rb.y;
                    float2 q;
                    q.x = v0; q.y = v1; *(float2*)(C + o0) = q;
                    q.x = v2; q.y = v3; *(float2*)(C + o1) = q;
                }
            }
        }
    }
}

// ---------------------------------------------------------------------------
// Merged weight convert + transpose for all 4 weights + W_off (one launch).
// ---------------------------------------------------------------------------
__global__ __launch_bounds__(256) void wconv_all(
    const float* __restrict__ W1, const float* __restrict__ W2,
    const float* __restrict__ Wf1, const float* __restrict__ Wf2,
    const float* __restrict__ Woff,
    __half* __restrict__ W1p, __half* __restrict__ W2p,
    __half* __restrict__ Wf1p, __half* __restrict__ Wf2p,
    __half* __restrict__ Woh)
{
    __shared__ float tile[32][33];
    const int bid = blockIdx.x;
    const int tx = threadIdx.x, ty = threadIdx.y;

    if (bid == 11264) {
        const int tid = ty * 32 + tx;
        for (int i = tid; i < 16384; i += 256) {
            const int n = i & 15, k = i >> 4;
            Woh[n * 1024 + k] = __float2half_rn(Woff[(size_t)k * 16 + n]);
        }
        return;
    }

    const float* W; __half* Wh;
    int K, N, n0, k0;
    bool perm = false;
    if (bid < 2048)       { perm = true; W = W1;  Wh = W1p;  K = 1024; N = 2048;
                            n0 = (bid & 63) << 5;  k0 = (bid >> 6) << 5; }
    else if (bid < 3072)  { const int r = bid - 2048; W = W2;  Wh = W2p;  K = 1024; N = 1024;
                            n0 = (r & 31) << 5;    k0 = (r >> 5) << 5; }
    else if (bid < 7168)  { const int r = bid - 3072; W = Wf1; Wh = Wf1p; K = 1024; N = 4096;
                            n0 = (r & 127) << 5;   k0 = (r >> 7) << 5; }
    else                  { const int r = bid - 7168; W = Wf2; Wh = Wf2p; K = 4096; N = 1024;
                            n0 = (r & 31) << 5;    k0 = (r >> 5) << 5; }

    if (perm) {
        const int orow = n0 + tx;
        const int scol = (orow & 1) ? (1024 + (orow >> 1)) : (orow >> 1);
        for (int i = ty; i < 32; i += 8)
            tile[i][tx] = W[(size_t)(k0 + i) * 2048 + scol];
    } else {
        for (int i = ty; i < 32; i += 8)
            tile[i][tx] = W[(size_t)(k0 + i) * N + n0 + tx];
    }
    __syncthreads();
    for (int i = ty; i < 32; i += 8)
        Wh[(size_t)(n0 + i) * K + k0 + tx] = __float2half_rn(tile[tx][i]);
}

// ---------------------------------------------------------------------------
// LayerNorm -> fp16, warp per row (no block barriers)
// ---------------------------------------------------------------------------
__global__ __launch_bounds__(256) void ln_h_kernel(
    const float* __restrict__ in, __half* __restrict__ oh,
    const float* __restrict__ gw, const float* __restrict__ bw)
{
    const int wid = threadIdx.x >> 5, lane = threadIdx.x & 31;
    const size_t row = (size_t)blockIdx.x * 8 + wid;
    const float4* ip = (const float4*)(in + row * 1024);

    float4 v[8];
    #pragma unroll
    for (int j = 0; j < 8; j++) v[j] = ip[j * 32 + lane];

    float s = 0.f;
    #pragma unroll
    for (int j = 0; j < 8; j++) s += v[j].x + v[j].y + v[j].z + v[j].w;
    #pragma unroll
    for (int o = 16; o > 0; o >>= 1) s += __shfl_xor_sync(0xffffffffu, s, o);
    const float mean = s * (1.f / 1024.f);

    float q = 0.f;
    #pragma unroll
    for (int j = 0; j < 8; j++) {
        const float dx = v[j].x - mean, dy = v[j].y - mean;
        const float dz = v[j].z - mean, dw = v[j].w - mean;
        q += dx * dx + dy * dy + dz * dz + dw * dw;
    }
    #pragma unroll
    for (int o = 16; o > 0; o >>= 1) q += __shfl_xor_sync(0xffffffffu, q, o);
    const float rstd = rsqrtf(q * (1.f / 1024.f) + 1e-5f);

    #pragma unroll
    for (int j = 0; j < 8; j++) {
        const int i4 = j * 32 + lane;
        const float4 g4 = __ldg((const float4*)gw + i4);
        const float4 b4 = __ldg((const float4*)bw + i4);
        const size_t base = row * 1024 + (size_t)i4 * 4;
        __half2 p;
        p.x = __float2half_rn((v[j].x - mean) * rstd * g4.x + b4.x);
        p.y = __float2half_rn((v[j].y - mean) * rstd * g4.y + b4.y);
        *(__half2*)(oh + base) = p;
        p.x = __float2half_rn((v[j].z - mean) * rstd * g4.z + b4.z);
        p.y = __float2half_rn((v[j].w - mean) * rstd * g4.w + b4.w);
        *(__half2*)(oh + base + 2) = p;
    }
}

// ---------------------------------------------------------------------------
// Merged alpha (mma.sync) + cumsum_part.
// Blocks [0,256): alpha — CTA = 128 rows, 8 warps x m16, N=16, BK=64,
//   3-stage cp.async ring for glu + Woh staged in padded smem rows (2064B).
// Blocks [256,512): partial segment sums.
// smem: ring 3*16KB at 0, Woh 16*2064B at 49152. Total 82176B.
// ---------------------------------------------------------------------------
#define AP_RING   16384
#define AP_WOH    (3 * AP_RING)
#define AP_SMEM   (AP_WOH + 16 * 2064)

__global__ __launch_bounds__(256) void alpha_part_kernel(
    const __half* __restrict__ g, const __half* __restrict__ Woh,
    const float* __restrict__ boff, float* __restrict__ alpha,
    float* __restrict__ part)
{
    if (blockIdx.x >= 256) {
        const int u = (blockIdx.x - 256) * 256 + threadIdx.x;
        const int c = u & 8191;
        const int s = u >> 13;
        float acc = 0.f;
        for (int t0 = s * 512; t0 < (s + 1) * 512; t0 += 8) {
            float v[8];
            #pragma unroll
            for (int i = 0; i < 8; i++)
                v[i] = __half2float(g[(size_t)(t0 + i) * CHAN + c]);
            #pragma unroll
            for (int i = 0; i < 8; i++) acc += v[i];
        }
        part[s * CHAN + c] = acc;
        return;
    }

    // ---- alpha via mma ----
    extern __shared__ __align__(1024) char smem[];
    const uint32_t sb = smem_addr_of(smem);
    const int tid = threadIdx.x, wid = tid >> 5, lane = tid & 31;
    const int m0 = blockIdx.x << 7;

    // stage Woh into padded rows (2064B = 1032 halves)
    __half* Wsm = (__half*)(smem + AP_WOH);
    for (int i = tid; i < 16384; i += 256)
        Wsm[(i >> 10) * 1032 + (i & 1023)] = Woh[i];

    const int ldr = tid >> 3;
    const int ldc = tid & 7;
    const uint32_t dst = (uint32_t)ldr * 128 + (((uint32_t)ldc ^ (ldr & 7)) << 4);

    auto load_stage = [&](uint32_t sbase, int chunk) {
        const __half* a = g + (size_t)(m0 + ldr) * 1024 + (chunk << 6) + (ldc << 3);
        #pragma unroll
        for (int i = 0; i < 4; i++)
            cpa16(sbase + dst + i * (32 * 128), a + (size_t)(i * 32) * 1024);
    };

    float acc[2][4];
    #pragma unroll
    for (int b = 0; b < 2; b++)
        #pragma unroll
        for (int k = 0; k < 4; k++) acc[b][k] = 0.f;

    uint32_t st0 = sb, st1 = sb + AP_RING, st2 = sb + 2 * AP_RING;
    load_stage(st0, 0); cpa_commit();
    load_stage(st1, 1); cpa_commit();

    const int ar = (wid << 4) + (lane & 15);
    const uint32_t aRow = (uint32_t)ar * 128;
    const int axor = ar & 7;
    const int ahalf = lane >> 4;
    const int brow = (lane & 7) | ((lane & 16) >> 1);
    const uint32_t bBase = sb + AP_WOH + (uint32_t)brow * 2064;
    const int bhalf = (lane >> 3) & 1;

    #pragma unroll 1
    for (int c = 0; c < 16; c++) {
        cpa_wait1();
        __syncthreads();
        if (c + 2 < 16) load_stage(st2, c + 2);
        cpa_commit();

        const uint32_t aH = st0 + aRow;
        #pragma unroll
        for (int kk = 0; kk < 4; kk++) {
            const uint32_t acol = (uint32_t)((((kk << 1) + ahalf) ^ axor)) << 4;
            uint32_t bh[4], a_f[4];
            ldsm4(bh, bBase + (uint32_t)(c * 128 + kk * 32 + bhalf * 16));
            ldsm4(a_f, aH + acol);
            mma16816h(acc[0], a_f, &bh[0]);
            mma16816h(acc[1], a_f, &bh[2]);
        }
        const uint32_t t = st0; st0 = st1; st1 = st2; st2 = t;
    }

    // epilogue: lane l -> rows (l>>2), (l>>2)+8 ; cols g*8 + (l&3)*2 + {0,1}
    const int rA = m0 + (wid << 4) + (lane >> 2);
    #pragma unroll
    for (int bgrp = 0; bgrp < 2; bgrp++) {
        const int n0 = (bgrp << 3) + ((lane & 3) << 1);
        const float b0 = __ldg(boff + n0);
        const float b1 = __ldg(boff + n0 + 1);
        #pragma unroll
        for (int h = 0; h < 2; h++) {
            const int row = rA + h * 8;
            const int t = row >> 3, bb = row & 7;
            float* ap = alpha + (size_t)t * BH_DIM + bb * 16;
            ap[n0]     = sigmoidf_(acc[bgrp][h * 2]     + b0);
            ap[n0 + 1] = sigmoidf_(acc[bgrp][h * 2 + 1] + b1);
        }
    }
}

// ---------------------------------------------------------------------------
// Fused cumsum-scan + TaLK (fp16 in/out), smem ring of S window.
// ---------------------------------------------------------------------------
__global__ __launch_bounds__(256) void scan_talk_kernel(
    const __half* __restrict__ in, const float* __restrict__ part,
    const float* __restrict__ alpha, __half* __restrict__ oh)
{
    extern __shared__ float ring[];   // [64][256]
    const int tidx = threadIdx.x;
    const int c = blockIdx.x * 256 + tidx;
    const int s = blockIdx.y;
    const int bh = c >> 6;
    const float scale = 1.f / 32.f;

    float acc = 0.f;
    for (int p = 0; p < s; p++) acc += part[p * CHAN + c];
    acc *= scale;

    const int tbase = s * 512;
    if (s > 0) {
        float w[34];
        #pragma unroll
        for (int i = 0; i < 34; i++)
            w[i] = __half2float(in[(size_t)(tbase - 34 + i) * CHAN + c]);
        float sub = 0.f;
        #pragma unroll
        for (int i = 0; i < 34; i++) sub += w[i];
        acc = acc - sub * scale;
        #pragma unroll
        for (int i = 0; i < 34; i++) {
            acc = fmaf(w[i], scale, acc);
            ring[((tbase - 34 + i) & 63) * 256 + tidx] = acc;
        }
    }

    for (int t0 = tbase; t0 < tbase + 512; t0 += 8) {
        float v[8];
        #pragma unroll
        for (int i = 0; i < 8; i++)
            v[i] = __half2float(in[(size_t)(t0 + i) * CHAN + c]);
        float sreg[8];
        #pragma unroll
        for (int i = 0; i < 8; i++) {
            acc = fmaf(v[i], scale, acc);
            sreg[i] = acc;
            ring[((t0 + i) & 63) * 256 + tidx] = acc;
        }
        float al[8];
        #pragma unroll
        for (int i = 0; i < 8; i++)
            al[i] = __ldg(alpha + (size_t)(t0 + i) * BH_DIM + bh);
        #pragma unroll
        for (int i = 0; i < 8; i++) {
            const int t = t0 + i;
            const float eff = fminf(31.f, (float)t);
            const float pos = (float)t - 1.f - al[i] * eff;
            const float i0f = floorf(pos);
            const float frac = pos - i0f;
            const int i0 = (int)i0f;
            const int c0 = max(i0, 0);
            const int c1 = i0 + 1;
            const float v0 = (i0 < 0) ? 0.f : ring[(c0 & 63) * 256 + tidx];
            const float v1 = ring[(c1 & 63) * 256 + tidx];
            const float out = sreg[i] - (v0 + frac * (v1 - v0));
            oh[(size_t)t * CHAN + c] = __float2half_rn(out);
        }
    }
}

// ---------------------------------------------------------------------------
// Launch (single stream, no host objects)
// ---------------------------------------------------------------------------
extern "C" void kernel_launch(void* const* d_in, const int* in_sizes, int n_in,
                              void* d_out, int out_size)
{
    const float* x    = (const float*)d_in[0];
    const float* W1   = (const float*)d_in[4];
    const float* b1   = (const float*)d_in[5];
    const float* Woff = (const float*)d_in[6];
    const float* boff = (const float*)d_in[7];
    const float* W2   = (const float*)d_in[8];
    const float* b2   = (const float*)d_in[9];
    const float* Wf1  = (const float*)d_in[10];
    const float* bf1  = (const float*)d_in[11];
    const float* Wf2  = (const float*)d_in[12];
    const float* bf2  = (const float*)d_in[13];
    const float* gcv  = (const float*)d_in[14];
    const float* bcv  = (const float*)d_in[15];
    const float* gfn  = (const float*)d_in[16];
    const float* bfn  = (const float*)d_in[17];

    __half *Ap, *Mp, *W1p, *W2p, *Wf1p, *Wf2p, *Woh, *glu;
    float *y, *alpha, *part;
    cudaGetSymbolAddress((void**)&Ap, g_A);
    cudaGetSymbolAddress((void**)&Mp, g_M);
    cudaGetSymbolAddress((void**)&W1p, g_W1);
    cudaGetSymbolAddress((void**)&W2p, g_W2);
    cudaGetSymbolAddress((void**)&Wf1p, g_Wf1);
    cudaGetSymbolAddress((void**)&Wf2p, g_Wf2);
    cudaGetSymbolAddress((void**)&Woh, g_Woh);
    cudaGetSymbolAddress((void**)&glu, g_glu);
    cudaGetSymbolAddress((void**)&y, g_y);
    cudaGetSymbolAddress((void**)&alpha, g_alpha);
    cudaGetSymbolAddress((void**)&part, g_part);

    cudaFuncSetAttribute((const void*)gemm_mma<1, 1024>, cudaFuncAttributeMaxDynamicSharedMemorySize, GEMM_SMEM);
    cudaFuncSetAttribute((const void*)gemm_mma<2, 1024>, cudaFuncAttributeMaxDynamicSharedMemorySize, GEMM_SMEM);
    cudaFuncSetAttribute((const void*)gemm_mma<3, 1024>, cudaFuncAttributeMaxDynamicSharedMemorySize, GEMM_SMEM);
    cudaFuncSetAttribute((const void*)gemm_mma<2, 4096>, cudaFuncAttributeMaxDynamicSharedMemorySize, GEMM_SMEM);
    cudaFuncSetAttribute(alpha_part_kernel, cudaFuncAttributeMaxDynamicSharedMemorySize, AP_SMEM);
    cudaFuncSetAttribute(scan_talk_kernel, cudaFuncAttributeMaxDynamicSharedMemorySize, 65536);

    // one launch: all weight conversions (+ W_off fp16 transpose)
    wconv_all<<<11265, dim3(32, 8)>>>(W1, W2, Wf1, Wf2, Woff,
                                      W1p, W2p, Wf1p, Wf2p, Woh);

    // conv block
    ln_h_kernel<<<M_TOK / 8, 256>>>(x, Ap, gcv, bcv);
    gemm_mma<3, 1024><<<dim3(16, 256), 256, GEMM_SMEM>>>(
        Ap, W1p, b1, nullptr, nullptr, glu, M_TOK, 2048);
    alpha_part_kernel<<<256 + 256, 256, AP_SMEM>>>(glu, Woh, boff, alpha, part);
    scan_talk_kernel<<<dim3(CHAN / 256, 8), 256, 65536>>>(glu, part, alpha, Ap);
    gemm_mma<2, 1024><<<dim3(8, 256), 256, GEMM_SMEM>>>(
        Ap, W2p, b2, x, y, nullptr, M_TOK, 1024);

    // FFN block
    ln_h_kernel<<<M_TOK / 8, 256>>>(y, Ap, gfn, bfn);
    gemm_mma<1, 1024><<<dim3(32, 256), 256, GEMM_SMEM>>>(
        Ap, Wf1p, bf1, nullptr, nullptr, Mp, M_TOK, 4096);
    gemm_mma<2, 4096><<<dim3(8, 256), 256, GEMM_SMEM>>>(
        Mp, Wf2p, bf2, y, (float*)d_out, nullptr, M_TOK, 1024);
}